// round 11
// baseline (speedup 1.0000x reference)
#include <cuda_runtime.h>

#define DD  1024
#define BB  128
#define LLn 196
#define LP1 197

// ---------------- scratch (no allocs allowed) ----------------
__device__ float g_fr [BB*DD];
__device__ float g_ho [BB*DD];
__device__ float g_att[BB*DD];
__device__ float g_scores[BB*LP1];
__device__ float g_part[8][BB*DD];   // GEMM K-split partials

// ---------------- helpers ----------------
__device__ __forceinline__ unsigned long long fma2(unsigned long long a,
                                                   unsigned long long b,
                                                   unsigned long long c) {
    unsigned long long r;
    asm("fma.rn.f32x2 %0, %1, %2, %3;" : "=l"(r) : "l"(a), "l"(b), "l"(c));
    return r;
}
__device__ __forceinline__ unsigned long long dup2(float x) {
    unsigned long long r;
    asm("mov.b64 %0, {%1, %1};" : "=l"(r) : "f"(x));
    return r;
}
__device__ __forceinline__ float tanh_fast(float x) {
    float y;
    asm("tanh.approx.f32 %0, %1;" : "=f"(y) : "f"(x));
    return y;
}

// ---------------- GEMM partial: P = A[:,ks] @ W[:,ks]^T ----------------
// BM=64, BN=128, BK=16, 256 threads (2 warps/SMSP), thread tile 4m x 8n.
// grid (8, 2, z): prob = z / ks_per_prob, koff = (z % ks_per_prob) * klen.
__global__ void __launch_bounds__(256)
gemm_kernel(const float* __restrict__ A0, const float* __restrict__ W0,
            const float* __restrict__ A1, const float* __restrict__ W1,
            int ks_per_prob, int klen)
{
    const int bz = blockIdx.z;
    const float* A = (bz < ks_per_prob) ? A0 : A1;
    const float* W = (bz < ks_per_prob) ? W0 : W1;
    const int koff = (bz % ks_per_prob) * klen;
    float* P = g_part[bz];

    __shared__ float As[2][16][72];           // 64 rows + pad
    __shared__ float Bs[2][16][136];          // 128 rows + pad

    const int t  = threadIdx.x;
    const int bn = blockIdx.x << 7;
    const int bm = blockIdx.y << 6;

    const int lrA = t >> 2, lcA = (t & 3) << 2;   // A: row 0..63, 1 float4
    const int lrB = t >> 1, lcB = (t & 1) << 3;   // B: row 0..127, 2 float4
    const float* Ap = A + (size_t)(bm + lrA) * DD + koff + lcA;
    const float* Wp = W + (size_t)(bn + lrB) * DD + koff + lcB;

    const int tx = t & 15, ty = t >> 4;
    const int m0 = ty << 2, n0 = tx << 3;

    unsigned long long acc[2][8];             // [m-pair][n]
#pragma unroll
    for (int i = 0; i < 2; i++)
#pragma unroll
        for (int j = 0; j < 8; j++) acc[i][j] = 0ull;

    float4 av  = *(const float4*)Ap;
    float4 wv0 = *(const float4*)Wp;
    float4 wv1 = *(const float4*)(Wp + 4);

    {
        float a[4] = {av.x, av.y, av.z, av.w};
        float w[8] = {wv0.x, wv0.y, wv0.z, wv0.w, wv1.x, wv1.y, wv1.z, wv1.w};
#pragma unroll
        for (int i = 0; i < 4; i++) As[0][lcA + i][lrA] = a[i];
#pragma unroll
        for (int i = 0; i < 8; i++) Bs[0][lcB + i][lrB] = w[i];
    }
    __syncthreads();

    const int nkb = klen >> 4;
    int buf = 0;
#pragma unroll 1
    for (int kb = 0; kb < nkb; kb++) {
        if (kb < nkb - 1) {
            av  = *(const float4*)(Ap + (kb + 1) * 16);
            wv0 = *(const float4*)(Wp + (kb + 1) * 16);
            wv1 = *(const float4*)(Wp + (kb + 1) * 16 + 4);
        }
#pragma unroll
        for (int k = 0; k < 16; k++) {
            union { float4 v; unsigned long long u[2]; } am;
            am.v = *(const float4*)&As[buf][k][m0];      // pairs (m0,m0+1),(m0+2,m0+3)
            float4 b0 = *(const float4*)&Bs[buf][k][n0];
            float4 b1 = *(const float4*)&Bs[buf][k][n0 + 4];
            unsigned long long bd[8] = {
                dup2(b0.x), dup2(b0.y), dup2(b0.z), dup2(b0.w),
                dup2(b1.x), dup2(b1.y), dup2(b1.z), dup2(b1.w) };
#pragma unroll
            for (int i = 0; i < 2; i++)
#pragma unroll
                for (int j = 0; j < 8; j++)
                    acc[i][j] = fma2(am.u[i], bd[j], acc[i][j]);
        }
        if (kb < nkb - 1) {
            const int nb = buf ^ 1;
            float a[4] = {av.x, av.y, av.z, av.w};
            float w[8] = {wv0.x, wv0.y, wv0.z, wv0.w, wv1.x, wv1.y, wv1.z, wv1.w};
#pragma unroll
            for (int i = 0; i < 4; i++) As[nb][lcA + i][lrA] = a[i];
#pragma unroll
            for (int i = 0; i < 8; i++) Bs[nb][lcB + i][lrB] = w[i];
            __syncthreads();
            buf = nb;
        }
    }

    // epilogue: acc[i][j] holds rows (m0+2i, m0+2i+1), col n0+j
#pragma unroll
    for (int i = 0; i < 2; i++) {
        float4 lo0, lo1, hi0, hi1;
        union { unsigned long long u; float f[2]; } c;
        c.u = acc[i][0]; lo0.x = c.f[0]; hi0.x = c.f[1];
        c.u = acc[i][1]; lo0.y = c.f[0]; hi0.y = c.f[1];
        c.u = acc[i][2]; lo0.z = c.f[0]; hi0.z = c.f[1];
        c.u = acc[i][3]; lo0.w = c.f[0]; hi0.w = c.f[1];
        c.u = acc[i][4]; lo1.x = c.f[0]; hi1.x = c.f[1];
        c.u = acc[i][5]; lo1.y = c.f[0]; hi1.y = c.f[1];
        c.u = acc[i][6]; lo1.z = c.f[0]; hi1.z = c.f[1];
        c.u = acc[i][7]; lo1.w = c.f[0]; hi1.w = c.f[1];
        float* r0 = P + (size_t)(bm + m0 + 2*i)     * DD + bn + n0;
        float* r1 = P + (size_t)(bm + m0 + 2*i + 1) * DD + bn + n0;
        *(float4*)r0       = lo0;  *(float4*)(r0 + 4) = lo1;
        *(float4*)r1       = hi0;  *(float4*)(r1 + 4) = hi1;
    }
}

// ---------------- combine4: dst = act(sum of 4 partials + bias), 2 problems ----
__global__ void __launch_bounds__(128)
combine4_kernel(float* __restrict__ dst0, const float* __restrict__ bias0, int act0,
                float* __restrict__ dst1, const float* __restrict__ bias1, int act1)
{
    const int p = blockIdx.y;
    float* dst        = p ? dst1  : dst0;
    const float* bias = p ? bias1 : bias0;
    const int act     = p ? act1  : act0;

    const int idx = blockIdx.x * 128 + threadIdx.x;
    float4 a = ((const float4*)g_part[4*p    ])[idx];
    float4 b = ((const float4*)g_part[4*p + 1])[idx];
    float4 cc = ((const float4*)g_part[4*p + 2])[idx];
    float4 d = ((const float4*)g_part[4*p + 3])[idx];
    float4 bi = ((const float4*)bias)[idx & 255];

    float o[4] = { (a.x + b.x) + (cc.x + d.x) + bi.x,
                   (a.y + b.y) + (cc.y + d.y) + bi.y,
                   (a.z + b.z) + (cc.z + d.z) + bi.z,
                   (a.w + b.w) + (cc.w + d.w) + bi.w };
    if (act == 1) {
#pragma unroll
        for (int j = 0; j < 4; j++) o[j] = fmaxf(o[j], 0.0f);
    } else {
#pragma unroll
        for (int j = 0; j < 4; j++) o[j] = tanhf(o[j]);
    }
    ((float4*)dst)[idx] = make_float4(o[0], o[1], o[2], o[3]);
}

// ---------------- combine8: dst = tanh(sum of 8 partials + bias) ----------------
__global__ void __launch_bounds__(128)
combine8_kernel(float* __restrict__ dst, const float* __restrict__ bias)
{
    const int idx = blockIdx.x * 128 + threadIdx.x;
    float s[4] = {0.f, 0.f, 0.f, 0.f};
#pragma unroll
    for (int q = 0; q < 8; q++) {
        float4 a = ((const float4*)g_part[q])[idx];
        s[0] += a.x; s[1] += a.y; s[2] += a.z; s[3] += a.w;
    }
    float4 bi = ((const float4*)bias)[idx & 255];
    ((float4*)dst)[idx] = make_float4(tanhf(s[0] + bi.x), tanhf(s[1] + bi.y),
                                      tanhf(s[2] + bi.z), tanhf(s[3] + bi.w));
}

// ---------------- scores (fused fre/hoe combine) ----------------
// hoe = part[4..7]+b_hoe built in smem per block; fre computed on the fly (l==0).
// scores[b,l] = Wa . tanh(row + hoe) + ba. grid (25, 128), 256 threads.
__global__ void __launch_bounds__(256)
scores_kernel(const float* __restrict__ embed,
              const float* __restrict__ Wa, const float* __restrict__ ba,
              const float* __restrict__ b_fre, const float* __restrict__ b_hoe)
{
    __shared__ float4 shoe[256];   // 1024 floats = hoe row for this b

    const int b = blockIdx.y;
    const int t = threadIdx.x;
    {
        const int idx = b * 256 + t;
        float4 p0 = ((const float4*)g_part[4])[idx];
        float4 p1 = ((const float4*)g_part[5])[idx];
        float4 p2 = ((const float4*)g_part[6])[idx];
        float4 p3 = ((const float4*)g_part[7])[idx];
        float4 bi = ((const float4*)b_hoe)[t];
        shoe[t] = make_float4((p0.x + p1.x) + (p2.x + p3.x) + bi.x,
                              (p0.y + p1.y) + (p2.y + p3.y) + bi.y,
                              (p0.z + p1.z) + (p2.z + p3.z) + bi.z,
                              (p0.w + p1.w) + (p2.w + p3.w) + bi.w);
    }
    __syncthreads();

    const int w    = t >> 5;
    const int lane = t & 31;
    const int l    = blockIdx.x * 8 + w;
    if (l >= LP1) return;

    float acc = 0.0f;
    if (l == 0) {
        // fre row computed on the fly from part[0..3] + b_fre
#pragma unroll
        for (int p = 0; p < 8; p++) {
            const int q = p * 32 + lane;           // float4 index within row
            const int idx = b * 256 + q;
            float4 e0 = ((const float4*)g_part[0])[idx];
            float4 e1 = ((const float4*)g_part[1])[idx];
            float4 e2 = ((const float4*)g_part[2])[idx];
            float4 e3 = ((const float4*)g_part[3])[idx];
            float4 bi = ((const float4*)b_fre)[q];
            float4 h  = shoe[q];
            float4 v  = ((const float4*)Wa)[q];
            float ex = (e0.x + e1.x) + (e2.x + e3.x) + bi.x;
            float ey = (e0.y + e1.y) + (e2.y + e3.y) + bi.y;
            float ez = (e0.z + e1.z) + (e2.z + e3.z) + bi.z;
            float ew = (e0.w + e1.w) + (e2.w + e3.w) + bi.w;
            acc = fmaf(tanh_fast(ex + h.x), v.x, acc);
            acc = fmaf(tanh_fast(ey + h.y), v.y, acc);
            acc = fmaf(tanh_fast(ez + h.z), v.z, acc);
            acc = fmaf(tanh_fast(ew + h.w), v.w, acc);
        }
    } else {
        const float* row = embed + ((size_t)b * LLn + (l - 1)) * DD;
#pragma unroll
        for (int p = 0; p < 8; p++) {
            const int q = p * 32 + lane;
            float4 e = ((const float4*)row)[q];
            float4 h = shoe[q];
            float4 v = ((const float4*)Wa)[q];
            acc = fmaf(tanh_fast(e.x + h.x), v.x, acc);
            acc = fmaf(tanh_fast(e.y + h.y), v.y, acc);
            acc = fmaf(tanh_fast(e.z + h.z), v.z, acc);
            acc = fmaf(tanh_fast(e.w + h.w), v.w, acc);
        }
    }
#pragma unroll
    for (int o = 16; o; o >>= 1) acc += __shfl_xor_sync(0xffffffffu, acc, o);
    if (lane == 0) g_scores[b * LP1 + l] = acc + ba[0];
}

// ---------------- fused softmax + weighted sum ----------------
__global__ void __launch_bounds__(256)
wsum_kernel(const float* __restrict__ conv)
{
    const int s = blockIdx.x, b = blockIdx.y, t = threadIdx.x;
    __shared__ float  sp[LP1];
    __shared__ float  red[8];
    __shared__ float4 red4[4][64];

    float v = (t < LP1) ? g_scores[b * LP1 + t] : -3.4e38f;
    float m = v;
#pragma unroll
    for (int o = 16; o; o >>= 1) m = fmaxf(m, __shfl_xor_sync(0xffffffffu, m, o));
    if ((t & 31) == 0) red[t >> 5] = m;
    __syncthreads();
    float mx = red[0];
#pragma unroll
    for (int i = 1; i < 8; i++) mx = fmaxf(mx, red[i]);
    __syncthreads();

    float e = (t < LP1) ? expf(v - mx) : 0.0f;
    float su = e;
#pragma unroll
    for (int o = 16; o; o >>= 1) su += __shfl_xor_sync(0xffffffffu, su, o);
    if ((t & 31) == 0) red[t >> 5] = su;
    __syncthreads();
    float tot = red[0] + red[1] + red[2] + red[3]
              + red[4] + red[5] + red[6] + red[7];
    if (t < LP1) sp[t] = e / tot;
    __syncthreads();

    const int c  = t & 63;
    const int lg = t >> 6;
    const int d0 = (s << 8) + (c << 2);
    const float* base = conv + (size_t)b * LLn * DD + d0;

    float4 acc = make_float4(0.f, 0.f, 0.f, 0.f);
    const int l0 = lg * 49;
#pragma unroll 1
    for (int u = 0; u < 12; u++) {
        const int l = l0 + (u << 2);
        float4 v0 = *(const float4*)(base + (size_t)(l + 0) * DD);
        float4 v1 = *(const float4*)(base + (size_t)(l + 1) * DD);
        float4 v2 = *(const float4*)(base + (size_t)(l + 2) * DD);
        float4 v3 = *(const float4*)(base + (size_t)(l + 3) * DD);
        float w0 = sp[l + 1], w1 = sp[l + 2], w2 = sp[l + 3], w3 = sp[l + 4];
        acc.x += v0.x*w0 + v1.x*w1 + v2.x*w2 + v3.x*w3;
        acc.y += v0.y*w0 + v1.y*w1 + v2.y*w2 + v3.y*w3;
        acc.z += v0.z*w0 + v1.z*w1 + v2.z*w2 + v3.z*w3;
        acc.w += v0.w*w0 + v1.w*w1 + v2.w*w2 + v3.w*w3;
    }
    {
        const int l = l0 + 48;
        float4 v0 = *(const float4*)(base + (size_t)l * DD);
        float w0 = sp[l + 1];
        acc.x += v0.x*w0; acc.y += v0.y*w0; acc.z += v0.z*w0; acc.w += v0.w*w0;
    }
    red4[lg][c] = acc;
    __syncthreads();

    if (lg == 0) {
        float4 r0 = red4[0][c], r1 = red4[1][c], r2 = red4[2][c], r3 = red4[3][c];
        float4 f = *(const float4*)(g_fr + (size_t)b * DD + d0);
        float4 h = *(const float4*)(g_ho + (size_t)b * DD + d0);
        float p0 = sp[0];
        float4 o;
        o.x = r0.x + r1.x + r2.x + r3.x + f.x * p0 + h.x;
        o.y = r0.y + r1.y + r2.y + r3.y + f.y * p0 + h.y;
        o.z = r0.z + r1.z + r2.z + r3.z + f.z * p0 + h.z;
        o.w = r0.w + r1.w + r2.w + r3.w + f.w * p0 + h.w;
        *(float4*)(g_att + (size_t)b * DD + d0) = o;
    }
}

// ---------------- host launcher ----------------
extern "C" void kernel_launch(void* const* d_in, const int* in_sizes, int n_in,
                              void* d_out, int out_size)
{
    (void)in_sizes; (void)n_in; (void)out_size;
    const float* h_out = (const float*)d_in[0];
    const float* fake  = (const float*)d_in[1];
    const float* conv  = (const float*)d_in[2];
    const float* embed = (const float*)d_in[3];
    const float* W_fr  = (const float*)d_in[4];
    const float* b_fr  = (const float*)d_in[5];
    const float* W_fre = (const float*)d_in[6];
    const float* b_fre = (const float*)d_in[7];
    const float* W_ho  = (const float*)d_in[8];
    const float* b_ho  = (const float*)d_in[9];
    const float* W_hoe = (const float*)d_in[10];
    const float* b_hoe = (const float*)d_in[11];
    const float* W_a   = (const float*)d_in[12];
    const float* b_a   = (const float*)d_in[13];
    const float* W_h   = (const float*)d_in[14];
    const float* b_h   = (const float*)d_in[15];

    float *fr, *ho, *att;
    cudaGetSymbolAddress((void**)&fr,  g_fr);
    cudaGetSymbolAddress((void**)&ho,  g_ho);
    cudaGetSymbolAddress((void**)&att, g_att);

    // stage 1: fr = relu(fake@W_fr^T + b), ho = tanh(h_out@W_ho^T + b)
    gemm_kernel<<<dim3(8, 2, 8), 256>>>(fake, W_fr, h_out, W_ho, 4, 256);
    combine4_kernel<<<dim3(256, 2), 128>>>(fr, b_fr, 1, ho, b_ho, 2);
    // stage 2: fre/hoe partials (combined inside scores)
    gemm_kernel<<<dim3(8, 2, 8), 256>>>(fr, W_fre, ho, W_hoe, 4, 256);
    // attention
    scores_kernel<<<dim3(25, BB), 256>>>(embed, W_a, b_a, b_fre, b_hoe);
    wsum_kernel<<<dim3(4, BB), 256>>>(conv);
    // stage 3: h = tanh(att@W_h^T + b_h), full-chip ksplit=8
    gemm_kernel<<<dim3(8, 2, 8), 256>>>(att, W_h, att, W_h, 8, 128);
    combine8_kernel<<<dim3(256, 1), 128>>>((float*)d_out, b_h);
}

// round 12
// speedup vs baseline: 1.2394x; 1.2394x over previous
#include <cuda_runtime.h>

#define DD  1024
#define BB  128
#define LLn 196
#define LP1 197

// ---------------- scratch (no allocs allowed) ----------------
__device__ float g_fr [BB*DD];
__device__ float g_fre[BB*DD];
__device__ float g_ho [BB*DD];
__device__ float g_hoe[BB*DD];
__device__ float g_att[BB*DD];
__device__ float g_scores[BB*LP1];
__device__ float g_part[8][BB*DD];   // GEMM K-split partials

// ---------------- helpers ----------------
__device__ __forceinline__ unsigned long long fma2(unsigned long long a,
                                                   unsigned long long b,
                                                   unsigned long long c) {
    unsigned long long r;
    asm("fma.rn.f32x2 %0, %1, %2, %3;" : "=l"(r) : "l"(a), "l"(b), "l"(c));
    return r;
}
__device__ __forceinline__ unsigned long long dup2(float x) {
    unsigned long long r;
    asm("mov.b64 %0, {%1, %1};" : "=l"(r) : "f"(x));
    return r;
}
__device__ __forceinline__ float tanh_fast(float x) {
    float y;
    asm("tanh.approx.f32 %0, %1;" : "=f"(y) : "f"(x));
    return y;
}

// ---------------- GEMM partial: P = A[:,ks] @ W[:,ks]^T ----------------
// BM=64, BN=128, BK=16, 256 threads (2 warps/SMSP), thread tile 4m x (4+4)n.
// Thread n-cols: [tx*4, tx*4+3] and [64+tx*4, 64+tx*4+3] -> conflict-free LDS.
// grid (8, 2, z): prob = z / ks_per_prob, koff = (z % ks_per_prob) * klen.
__global__ void __launch_bounds__(256)
gemm_kernel(const float* __restrict__ A0, const float* __restrict__ W0,
            const float* __restrict__ A1, const float* __restrict__ W1,
            int ks_per_prob, int klen)
{
    const int bz = blockIdx.z;
    const float* A = (bz < ks_per_prob) ? A0 : A1;
    const float* W = (bz < ks_per_prob) ? W0 : W1;
    const int koff = (bz % ks_per_prob) * klen;
    float* P = g_part[bz];

    __shared__ float As[2][16][72];           // 64 rows + pad
    __shared__ float Bs[2][16][132];          // 128 rows + pad

    const int t  = threadIdx.x;
    const int bn = blockIdx.x << 7;
    const int bm = blockIdx.y << 6;

    const int lrA = t >> 2, lcA = (t & 3) << 2;   // A: row 0..63, 1 float4
    const int lrB = t >> 1, lcB = (t & 1) << 3;   // B: row 0..127, 2 float4
    const float* Ap = A + (size_t)(bm + lrA) * DD + koff + lcA;
    const float* Wp = W + (size_t)(bn + lrB) * DD + koff + lcB;

    const int tx = t & 15, ty = t >> 4;
    const int m0 = ty << 2, n0 = tx << 2;

    unsigned long long acc[2][8];             // [m-pair][j]  j<4: n0+j ; j>=4: 64+n0+j-4
#pragma unroll
    for (int i = 0; i < 2; i++)
#pragma unroll
        for (int j = 0; j < 8; j++) acc[i][j] = 0ull;

    float4 av  = *(const float4*)Ap;
    float4 wv0 = *(const float4*)Wp;
    float4 wv1 = *(const float4*)(Wp + 4);

    {
        float a[4] = {av.x, av.y, av.z, av.w};
        float w[8] = {wv0.x, wv0.y, wv0.z, wv0.w, wv1.x, wv1.y, wv1.z, wv1.w};
#pragma unroll
        for (int i = 0; i < 4; i++) As[0][lcA + i][lrA] = a[i];
#pragma unroll
        for (int i = 0; i < 8; i++) Bs[0][lcB + i][lrB] = w[i];
    }
    __syncthreads();

    const int nkb = klen >> 4;
    int buf = 0;
#pragma unroll 1
    for (int kb = 0; kb < nkb; kb++) {
        if (kb < nkb - 1) {
            av  = *(const float4*)(Ap + (kb + 1) * 16);
            wv0 = *(const float4*)(Wp + (kb + 1) * 16);
            wv1 = *(const float4*)(Wp + (kb + 1) * 16 + 4);
        }
#pragma unroll
        for (int k = 0; k < 16; k++) {
            union { float4 v; unsigned long long u[2]; } am;
            am.v = *(const float4*)&As[buf][k][m0];      // m-pairs (m0,m0+1),(m0+2,m0+3)
            float4 b0 = *(const float4*)&Bs[buf][k][n0];        // contiguous 256B/warp
            float4 b1 = *(const float4*)&Bs[buf][k][n0 + 64];   // contiguous 256B/warp
            unsigned long long bd[8] = {
                dup2(b0.x), dup2(b0.y), dup2(b0.z), dup2(b0.w),
                dup2(b1.x), dup2(b1.y), dup2(b1.z), dup2(b1.w) };
#pragma unroll
            for (int i = 0; i < 2; i++)
#pragma unroll
                for (int j = 0; j < 8; j++)
                    acc[i][j] = fma2(am.u[i], bd[j], acc[i][j]);
        }
        if (kb < nkb - 1) {
            const int nb = buf ^ 1;
            float a[4] = {av.x, av.y, av.z, av.w};
            float w[8] = {wv0.x, wv0.y, wv0.z, wv0.w, wv1.x, wv1.y, wv1.z, wv1.w};
#pragma unroll
            for (int i = 0; i < 4; i++) As[nb][lcA + i][lrA] = a[i];
#pragma unroll
            for (int i = 0; i < 8; i++) Bs[nb][lcB + i][lrB] = w[i];
            __syncthreads();
            buf = nb;
        }
    }

    // epilogue: acc[i][j] holds rows (m0+2i, m0+2i+1); j<4 -> col n0+j, j>=4 -> col 64+n0+j-4
#pragma unroll
    for (int i = 0; i < 2; i++) {
        float4 lo0, lo1, hi0, hi1;
        union { unsigned long long u; float f[2]; } c;
        c.u = acc[i][0]; lo0.x = c.f[0]; hi0.x = c.f[1];
        c.u = acc[i][1]; lo0.y = c.f[0]; hi0.y = c.f[1];
        c.u = acc[i][2]; lo0.z = c.f[0]; hi0.z = c.f[1];
        c.u = acc[i][3]; lo0.w = c.f[0]; hi0.w = c.f[1];
        c.u = acc[i][4]; lo1.x = c.f[0]; hi1.x = c.f[1];
        c.u = acc[i][5]; lo1.y = c.f[0]; hi1.y = c.f[1];
        c.u = acc[i][6]; lo1.z = c.f[0]; hi1.z = c.f[1];
        c.u = acc[i][7]; lo1.w = c.f[0]; hi1.w = c.f[1];
        float* r0 = P + (size_t)(bm + m0 + 2*i)     * DD + bn;
        float* r1 = P + (size_t)(bm + m0 + 2*i + 1) * DD + bn;
        *(float4*)(r0 + n0)      = lo0;  *(float4*)(r0 + 64 + n0) = lo1;
        *(float4*)(r1 + n0)      = hi0;  *(float4*)(r1 + 64 + n0) = hi1;
    }
}

// ---------------- combine4: dst = act(sum of 4 partials + bias), 2 problems ----
__global__ void __launch_bounds__(128)
combine4_kernel(float* __restrict__ dst0, const float* __restrict__ bias0, int act0,
                float* __restrict__ dst1, const float* __restrict__ bias1, int act1)
{
    const int p = blockIdx.y;
    float* dst        = p ? dst1  : dst0;
    const float* bias = p ? bias1 : bias0;
    const int act     = p ? act1  : act0;

    const int idx = blockIdx.x * 128 + threadIdx.x;
    float4 a = ((const float4*)g_part[4*p    ])[idx];
    float4 b = ((const float4*)g_part[4*p + 1])[idx];
    float4 cc = ((const float4*)g_part[4*p + 2])[idx];
    float4 d = ((const float4*)g_part[4*p + 3])[idx];
    float4 bi = ((const float4*)bias)[idx & 255];

    float o[4] = { (a.x + b.x) + (cc.x + d.x) + bi.x,
                   (a.y + b.y) + (cc.y + d.y) + bi.y,
                   (a.z + b.z) + (cc.z + d.z) + bi.z,
                   (a.w + b.w) + (cc.w + d.w) + bi.w };
    if (act == 1) {
#pragma unroll
        for (int j = 0; j < 4; j++) o[j] = fmaxf(o[j], 0.0f);
    } else if (act == 2) {
#pragma unroll
        for (int j = 0; j < 4; j++) o[j] = tanhf(o[j]);
    }
    ((float4*)dst)[idx] = make_float4(o[0], o[1], o[2], o[3]);
}

// ---------------- combine8: dst = tanh(sum of 8 partials + bias) ----------------
__global__ void __launch_bounds__(128)
combine8_kernel(float* __restrict__ dst, const float* __restrict__ bias)
{
    const int idx = blockIdx.x * 128 + threadIdx.x;
    float s[4] = {0.f, 0.f, 0.f, 0.f};
#pragma unroll
    for (int q = 0; q < 8; q++) {
        float4 a = ((const float4*)g_part[q])[idx];
        s[0] += a.x; s[1] += a.y; s[2] += a.z; s[3] += a.w;
    }
    float4 bi = ((const float4*)bias)[idx & 255];
    ((float4*)dst)[idx] = make_float4(tanhf(s[0] + bi.x), tanhf(s[1] + bi.y),
                                      tanhf(s[2] + bi.z), tanhf(s[3] + bi.w));
}

// ---------------- scores[b,l] = Wa . tanh(E[b,l,:] + hoe[b,:]) + ba ----------------
// One warp per l, contiguous float4 per lane. grid (25, 128), 256 threads.
__global__ void __launch_bounds__(256)
scores_kernel(const float* __restrict__ embed,
              const float* __restrict__ Wa, const float* __restrict__ ba)
{
    const int b    = blockIdx.y;
    const int t    = threadIdx.x;
    const int w    = t >> 5;
    const int lane = t & 31;
    const int l    = blockIdx.x * 8 + w;
    if (l >= LP1) return;

    const float* row  = (l == 0) ? (g_fre + (size_t)b * DD)
                                 : (embed + ((size_t)b * LLn + (l - 1)) * DD);
    const float* hrow = g_hoe + (size_t)b * DD;

    float acc = 0.0f;
#pragma unroll
    for (int p = 0; p < 8; p++) {
        const int d = p * 128 + lane * 4;
        float4 e = *(const float4*)(row  + d);
        float4 h = *(const float4*)(hrow + d);
        float4 v = *(const float4*)(Wa   + d);
        acc = fmaf(tanh_fast(e.x + h.x), v.x, acc);
        acc = fmaf(tanh_fast(e.y + h.y), v.y, acc);
        acc = fmaf(tanh_fast(e.z + h.z), v.z, acc);
        acc = fmaf(tanh_fast(e.w + h.w), v.w, acc);
    }
#pragma unroll
    for (int o = 16; o; o >>= 1) acc += __shfl_xor_sync(0xffffffffu, acc, o);
    if (lane == 0) g_scores[b * LP1 + l] = acc + ba[0];
}

// ---------------- fused softmax + weighted sum ----------------
__global__ void __launch_bounds__(256)
wsum_kernel(const float* __restrict__ conv)
{
    const int s = blockIdx.x, b = blockIdx.y, t = threadIdx.x;
    __shared__ float  sp[LP1];
    __shared__ float  red[8];
    __shared__ float4 red4[4][64];

    float v = (t < LP1) ? g_scores[b * LP1 + t] : -3.4e38f;
    float m = v;
#pragma unroll
    for (int o = 16; o; o >>= 1) m = fmaxf(m, __shfl_xor_sync(0xffffffffu, m, o));
    if ((t & 31) == 0) red[t >> 5] = m;
    __syncthreads();
    float mx = red[0];
#pragma unroll
    for (int i = 1; i < 8; i++) mx = fmaxf(mx, red[i]);
    __syncthreads();

    float e = (t < LP1) ? expf(v - mx) : 0.0f;
    float su = e;
#pragma unroll
    for (int o = 16; o; o >>= 1) su += __shfl_xor_sync(0xffffffffu, su, o);
    if ((t & 31) == 0) red[t >> 5] = su;
    __syncthreads();
    float tot = red[0] + red[1] + red[2] + red[3]
              + red[4] + red[5] + red[6] + red[7];
    if (t < LP1) sp[t] = e / tot;
    __syncthreads();

    const int c  = t & 63;
    const int lg = t >> 6;
    const int d0 = (s << 8) + (c << 2);
    const float* base = conv + (size_t)b * LLn * DD + d0;

    float4 acc = make_float4(0.f, 0.f, 0.f, 0.f);
    const int l0 = lg * 49;
#pragma unroll 1
    for (int u = 0; u < 12; u++) {
        const int l = l0 + (u << 2);
        float4 v0 = *(const float4*)(base + (size_t)(l + 0) * DD);
        float4 v1 = *(const float4*)(base + (size_t)(l + 1) * DD);
        float4 v2 = *(const float4*)(base + (size_t)(l + 2) * DD);
        float4 v3 = *(const float4*)(base + (size_t)(l + 3) * DD);
        float w0 = sp[l + 1], w1 = sp[l + 2], w2 = sp[l + 3], w3 = sp[l + 4];
        acc.x += v0.x*w0 + v1.x*w1 + v2.x*w2 + v3.x*w3;
        acc.y += v0.y*w0 + v1.y*w1 + v2.y*w2 + v3.y*w3;
        acc.z += v0.z*w0 + v1.z*w1 + v2.z*w2 + v3.z*w3;
        acc.w += v0.w*w0 + v1.w*w1 + v2.w*w2 + v3.w*w3;
    }
    {
        const int l = l0 + 48;
        float4 v0 = *(const float4*)(base + (size_t)l * DD);
        float w0 = sp[l + 1];
        acc.x += v0.x*w0; acc.y += v0.y*w0; acc.z += v0.z*w0; acc.w += v0.w*w0;
    }
    red4[lg][c] = acc;
    __syncthreads();

    if (lg == 0) {
        float4 r0 = red4[0][c], r1 = red4[1][c], r2 = red4[2][c], r3 = red4[3][c];
        float4 f = *(const float4*)(g_fr + (size_t)b * DD + d0);
        float4 h = *(const float4*)(g_ho + (size_t)b * DD + d0);
        float p0 = sp[0];
        float4 o;
        o.x = r0.x + r1.x + r2.x + r3.x + f.x * p0 + h.x;
        o.y = r0.y + r1.y + r2.y + r3.y + f.y * p0 + h.y;
        o.z = r0.z + r1.z + r2.z + r3.z + f.z * p0 + h.z;
        o.w = r0.w + r1.w + r2.w + r3.w + f.w * p0 + h.w;
        *(float4*)(g_att + (size_t)b * DD + d0) = o;
    }
}

// ---------------- host launcher ----------------
extern "C" void kernel_launch(void* const* d_in, const int* in_sizes, int n_in,
                              void* d_out, int out_size)
{
    (void)in_sizes; (void)n_in; (void)out_size;
    const float* h_out = (const float*)d_in[0];
    const float* fake  = (const float*)d_in[1];
    const float* conv  = (const float*)d_in[2];
    const float* embed = (const float*)d_in[3];
    const float* W_fr  = (const float*)d_in[4];
    const float* b_fr  = (const float*)d_in[5];
    const float* W_fre = (const float*)d_in[6];
    const float* b_fre = (const float*)d_in[7];
    const float* W_ho  = (const float*)d_in[8];
    const float* b_ho  = (const float*)d_in[9];
    const float* W_hoe = (const float*)d_in[10];
    const float* b_hoe = (const float*)d_in[11];
    const float* W_a   = (const float*)d_in[12];
    const float* b_a   = (const float*)d_in[13];
    const float* W_h   = (const float*)d_in[14];
    const float* b_h   = (const float*)d_in[15];

    float *fr, *fre, *ho, *hoe, *att;
    cudaGetSymbolAddress((void**)&fr,  g_fr);
    cudaGetSymbolAddress((void**)&fre, g_fre);
    cudaGetSymbolAddress((void**)&ho,  g_ho);
    cudaGetSymbolAddress((void**)&hoe, g_hoe);
    cudaGetSymbolAddress((void**)&att, g_att);

    // stage 1: fr = relu(fake@W_fr^T + b), ho = tanh(h_out@W_ho^T + b)
    gemm_kernel<<<dim3(8, 2, 8), 256>>>(fake, W_fr, h_out, W_ho, 4, 256);
    combine4_kernel<<<dim3(256, 2), 128>>>(fr, b_fr, 1, ho, b_ho, 2);
    // stage 2: fre = fr@W_fre^T + b, hoe = ho@W_hoe^T + b
    gemm_kernel<<<dim3(8, 2, 8), 256>>>(fr, W_fre, ho, W_hoe, 4, 256);
    combine4_kernel<<<dim3(256, 2), 128>>>(fre, b_fre, 0, hoe, b_hoe, 0);
    // attention
    scores_kernel<<<dim3(25, BB), 256>>>(embed, W_a, b_a);
    wsum_kernel<<<dim3(4, BB), 256>>>(conv);
    // stage 3: h = tanh(att@W_h^T + b_h), full-chip ksplit=8
    gemm_kernel<<<dim3(8, 2, 8), 256>>>(att, W_h, att, W_h, 8, 128);
    combine8_kernel<<<dim3(256, 1), 128>>>((float*)d_out, b_h);
}